// round 1
// baseline (speedup 1.0000x reference)
#include <cuda_runtime.h>

// Problem constants
#define DD   1024
#define EE   8
#define HH   2048
#define NN   8192   // B*T tokens

#define BM 64
#define BN 64
#define BK 16
#define AS 68   // padded A stride (68*4B = 272B = 17*16B: float4-aligned, conflict-reduced)

// ---- static device scratch (no allocation allowed in kernel_launch) ----
__device__ int   g_cnt[EE];
__device__ int   g_tok[EE * NN];
__device__ float g_gate[EE * NN];
__device__ float g_hbuf[(size_t)EE * NN * HH];   // 512 MB activation scratch

// ---------------------------------------------------------------------------
// Kernel 0: zero output + reset per-expert counters (needed every graph replay)
// ---------------------------------------------------------------------------
__global__ void zero_kernel(float4* __restrict__ out) {
    int i = blockIdx.x * blockDim.x + threadIdx.x;
    out[i] = make_float4(0.f, 0.f, 0.f, 0.f);
    if (blockIdx.x == 0 && threadIdx.x < EE) g_cnt[threadIdx.x] = 0;
}

// ---------------------------------------------------------------------------
// Kernel 1: router — logits, top-2, softmax, scatter token->expert lists
// one block (256 threads) per token
// ---------------------------------------------------------------------------
__global__ __launch_bounds__(256) void router_kernel(const float* __restrict__ x,
                                                     const float* __restrict__ rw) {
    int n   = blockIdx.x;
    int tid = threadIdx.x;
    const float* xr = x + (size_t)n * DD;

    float acc[EE];
#pragma unroll
    for (int e = 0; e < EE; e++) acc[e] = 0.f;

    for (int i = tid; i < DD; i += 256) {
        float xv = xr[i];
#pragma unroll
        for (int e = 0; e < EE; e++) acc[e] += xv * rw[e * DD + i];
    }

    // warp reduce all 8 accumulators
#pragma unroll
    for (int e = 0; e < EE; e++) {
#pragma unroll
        for (int o = 16; o > 0; o >>= 1)
            acc[e] += __shfl_down_sync(0xffffffffu, acc[e], o);
    }

    __shared__ float sm[8][EE];
    int warp = tid >> 5, lane = tid & 31;
    if (lane == 0) {
#pragma unroll
        for (int e = 0; e < EE; e++) sm[warp][e] = acc[e];
    }
    __syncthreads();

    if (tid == 0) {
        float logits[EE];
#pragma unroll
        for (int e = 0; e < EE; e++) {
            float s = 0.f;
#pragma unroll
            for (int w = 0; w < 8; w++) s += sm[w][e];
            logits[e] = s;
        }
        // top-2 (earliest index wins ties, matching lax.top_k)
        int i0 = 0; float v0 = logits[0];
#pragma unroll
        for (int e = 1; e < EE; e++) if (logits[e] > v0) { v0 = logits[e]; i0 = e; }
        int i1 = 0; float v1 = -3.0e38f;
#pragma unroll
        for (int e = 0; e < EE; e++) if (e != i0 && logits[e] > v1) { v1 = logits[e]; i1 = e; }

        float ex = __expf(v1 - v0);          // <= 1
        float g0 = 1.f / (1.f + ex);
        float g1 = ex * g0;

        int p0 = atomicAdd(&g_cnt[i0], 1);
        g_tok[i0 * NN + p0]  = n;
        g_gate[i0 * NN + p0] = g0;
        int p1 = atomicAdd(&g_cnt[i1], 1);
        g_tok[i1 * NN + p1]  = n;
        g_gate[i1 * NN + p1] = g1;
    }
}

// ---------------------------------------------------------------------------
// Kernel 2: pass A — h[e, slot, :] = relu(x[tok] @ w1[e])^2
// 64x64 tile, K-chunk 16, 256 threads, 4x4 micro-tile per thread
// grid: (HH/BN, NN/BM, EE); blocks beyond cnt[e] exit early
// ---------------------------------------------------------------------------
__global__ __launch_bounds__(256) void ffn1_kernel(const float* __restrict__ x,
                                                   const float* __restrict__ w1) {
    int e   = blockIdx.z;
    int cnt = g_cnt[e];
    int m0  = blockIdx.y * BM;
    if (m0 >= cnt) return;
    int n0  = blockIdx.x * BN;

    __shared__ __align__(16) float As[BK][AS];   // transposed: As[k][m]
    __shared__ __align__(16) float Bs[BK][BN];

    int tid = threadIdx.x;

    // A load: thread -> (row am, k-quad akq). Gathered token row.
    int am   = tid >> 2;
    int akq  = (tid & 3) * 4;
    int mrow = m0 + am;
    int mcl  = (mrow < cnt) ? mrow : (cnt - 1);
    int tokr = g_tok[e * NN + mcl];
    const float* aptr = x + (size_t)tokr * DD + akq;

    // B load: thread -> (k-row bkr, col quad bc) of w1[e]
    int bkr = tid >> 4;
    int bc  = (tid & 15) * 4;
    const float* bptr = w1 + (size_t)e * DD * HH + n0 + bc;

    int ty = tid >> 4;   // 0..15 -> rows ty*4..+3
    int tx = tid & 15;   // 0..15 -> cols tx*4..+3

    float c00=0,c01=0,c02=0,c03=0, c10=0,c11=0,c12=0,c13=0;
    float c20=0,c21=0,c22=0,c23=0, c30=0,c31=0,c32=0,c33=0;

    for (int k0 = 0; k0 < DD; k0 += BK) {
        float4 av = *(const float4*)(aptr + k0);
        float4 bv = *(const float4*)(bptr + (size_t)(k0 + bkr) * HH);
        As[akq + 0][am] = av.x;
        As[akq + 1][am] = av.y;
        As[akq + 2][am] = av.z;
        As[akq + 3][am] = av.w;
        *(float4*)&Bs[bkr][bc] = bv;
        __syncthreads();
#pragma unroll
        for (int kk = 0; kk < BK; kk++) {
            float4 a = *(const float4*)&As[kk][ty * 4];
            float4 b = *(const float4*)&Bs[kk][tx * 4];
            c00 += a.x*b.x; c01 += a.x*b.y; c02 += a.x*b.z; c03 += a.x*b.w;
            c10 += a.y*b.x; c11 += a.y*b.y; c12 += a.y*b.z; c13 += a.y*b.w;
            c20 += a.z*b.x; c21 += a.z*b.y; c22 += a.z*b.z; c23 += a.z*b.w;
            c30 += a.w*b.x; c31 += a.w*b.y; c32 += a.w*b.z; c33 += a.w*b.w;
        }
        __syncthreads();
    }

    float cc[4][4] = {{c00,c01,c02,c03},{c10,c11,c12,c13},
                      {c20,c21,c22,c23},{c30,c31,c32,c33}};
#pragma unroll
    for (int i = 0; i < 4; i++) {
        int m = m0 + ty * 4 + i;
        if (m < cnt) {
            float4 o;
            float r;
            r = cc[i][0]; r = r > 0.f ? r : 0.f; o.x = r * r;
            r = cc[i][1]; r = r > 0.f ? r : 0.f; o.y = r * r;
            r = cc[i][2]; r = r > 0.f ? r : 0.f; o.z = r * r;
            r = cc[i][3]; r = r > 0.f ? r : 0.f; o.w = r * r;
            *(float4*)(g_hbuf + ((size_t)e * NN + m) * HH + n0 + tx * 4) = o;
        }
    }
}

// ---------------------------------------------------------------------------
// Kernel 3: pass B — out[tok] += gate * (h[e,slot,:] @ w2[e])
// grid: (DD/BN, NN/BM, EE)
// ---------------------------------------------------------------------------
__global__ __launch_bounds__(256) void ffn2_kernel(const float* __restrict__ w2,
                                                   float* __restrict__ out) {
    int e   = blockIdx.z;
    int cnt = g_cnt[e];
    int m0  = blockIdx.y * BM;
    if (m0 >= cnt) return;
    int n0  = blockIdx.x * BN;

    __shared__ __align__(16) float As[BK][AS];
    __shared__ __align__(16) float Bs[BK][BN];

    int tid = threadIdx.x;

    int am   = tid >> 2;
    int akq  = (tid & 3) * 4;
    int mrow = m0 + am;
    int mcl  = (mrow < cnt) ? mrow : (cnt - 1);
    const float* aptr = g_hbuf + ((size_t)e * NN + mcl) * HH + akq;

    int bkr = tid >> 4;
    int bc  = (tid & 15) * 4;
    const float* bptr = w2 + (size_t)e * HH * DD + n0 + bc;

    int ty = tid >> 4;
    int tx = tid & 15;

    float c00=0,c01=0,c02=0,c03=0, c10=0,c11=0,c12=0,c13=0;
    float c20=0,c21=0,c22=0,c23=0, c30=0,c31=0,c32=0,c33=0;

    for (int k0 = 0; k0 < HH; k0 += BK) {
        float4 av = *(const float4*)(aptr + k0);
        float4 bv = *(const float4*)(bptr + (size_t)(k0 + bkr) * DD);
        As[akq + 0][am] = av.x;
        As[akq + 1][am] = av.y;
        As[akq + 2][am] = av.z;
        As[akq + 3][am] = av.w;
        *(float4*)&Bs[bkr][bc] = bv;
        __syncthreads();
#pragma unroll
        for (int kk = 0; kk < BK; kk++) {
            float4 a = *(const float4*)&As[kk][ty * 4];
            float4 b = *(const float4*)&Bs[kk][tx * 4];
            c00 += a.x*b.x; c01 += a.x*b.y; c02 += a.x*b.z; c03 += a.x*b.w;
            c10 += a.y*b.x; c11 += a.y*b.y; c12 += a.y*b.z; c13 += a.y*b.w;
            c20 += a.z*b.x; c21 += a.z*b.y; c22 += a.z*b.z; c23 += a.z*b.w;
            c30 += a.w*b.x; c31 += a.w*b.y; c32 += a.w*b.z; c33 += a.w*b.w;
        }
        __syncthreads();
    }

    float cc[4][4] = {{c00,c01,c02,c03},{c10,c11,c12,c13},
                      {c20,c21,c22,c23},{c30,c31,c32,c33}};
#pragma unroll
    for (int i = 0; i < 4; i++) {
        int m = m0 + ty * 4 + i;
        if (m < cnt) {
            int   tok  = g_tok[e * NN + m];
            float gate = g_gate[e * NN + m];
            float* orow = out + (size_t)tok * DD + n0 + tx * 4;
#pragma unroll
            for (int j = 0; j < 4; j++)
                atomicAdd(orow + j, gate * cc[i][j]);
        }
    }
}

// ---------------------------------------------------------------------------
extern "C" void kernel_launch(void* const* d_in, const int* in_sizes, int n_in,
                              void* d_out, int out_size) {
    const float* x  = (const float*)d_in[0];   // (B,T,D)
    const float* rw = (const float*)d_in[1];   // (E,D)
    const float* w1 = (const float*)d_in[2];   // (E,D,H)
    const float* w2 = (const float*)d_in[3];   // (E,H,D)
    float* out = (float*)d_out;                // (B,T,D) fp32

    int zblocks = out_size / (4 * 256);        // out_size = 8388608 -> 8192 blocks
    zero_kernel<<<zblocks, 256>>>((float4*)out);
    router_kernel<<<NN, 256>>>(x, rw);
    ffn1_kernel<<<dim3(HH / BN, NN / BM, EE), 256>>>(x, w1);
    ffn2_kernel<<<dim3(DD / BN, NN / BM, EE), 256>>>(w2, out);
}

// round 3
// speedup vs baseline: 2.1682x; 2.1682x over previous
#include <cuda_runtime.h>
#include <cuda_bf16.h>
#include <cstdint>

// ---------------- problem constants ----------------
#define DD   1024
#define EE   8
#define HH   2048
#define NN   8192   // B*T tokens

// GEMM tile config
#define TM   128
#define TN   128
#define TK   32                      // K elems per pipeline chunk
#define STAGES 4
#define STAGE_BYTES 32768            // Ahi8K+Alo8K+Bhi8K+Blo8K
#define SMEM_BYTES  (STAGES*STAGE_BYTES)   // 128 KB

// ---------------- static device scratch ----------------
__device__ int   g_cnt[EE];
__device__ int   g_tok[EE * NN];
__device__ float g_gate[EE * NN];
__device__ __nv_bfloat16 g_xg_hi[(size_t)EE * NN * DD];
__device__ __nv_bfloat16 g_xg_lo[(size_t)EE * NN * DD];
__device__ __nv_bfloat16 g_h_hi [(size_t)EE * NN * HH];
__device__ __nv_bfloat16 g_h_lo [(size_t)EE * NN * HH];
__device__ __nv_bfloat16 g_w1t_hi[(size_t)EE * DD * HH];
__device__ __nv_bfloat16 g_w1t_lo[(size_t)EE * DD * HH];
__device__ __nv_bfloat16 g_w2t_hi[(size_t)EE * HH * DD];
__device__ __nv_bfloat16 g_w2t_lo[(size_t)EE * HH * DD];

// ---------------- helpers ----------------
__device__ __forceinline__ uint32_t smem_u32(const void* p) {
    uint32_t a;
    asm("{ .reg .u64 t; cvta.to.shared.u64 t, %1; cvt.u32.u64 %0, t; }" : "=r"(a) : "l"(p));
    return a;
}
__device__ __forceinline__ void cp16(uint32_t s, const void* g) {
    asm volatile("cp.async.cg.shared.global [%0], [%1], 16;" :: "r"(s), "l"(g));
}
#define CP_COMMIT() asm volatile("cp.async.commit_group;" ::: "memory")
#define CP_WAIT(n)  asm volatile("cp.async.wait_group %0;" :: "n"(n) : "memory")

__device__ __forceinline__ void ldsm4(uint32_t* r, uint32_t a) {
    asm volatile("ldmatrix.sync.aligned.m8n8.x4.shared.b16 {%0,%1,%2,%3}, [%4];"
                 : "=r"(r[0]), "=r"(r[1]), "=r"(r[2]), "=r"(r[3]) : "r"(a));
}
__device__ __forceinline__ void mma16816(float* c, const uint32_t* a, uint32_t b0, uint32_t b1) {
    asm volatile("mma.sync.aligned.m16n8k16.row.col.f32.bf16.bf16.f32 "
                 "{%0,%1,%2,%3}, {%4,%5,%6,%7}, {%8,%9}, {%0,%1,%2,%3};"
                 : "+f"(c[0]), "+f"(c[1]), "+f"(c[2]), "+f"(c[3])
                 : "r"(a[0]), "r"(a[1]), "r"(a[2]), "r"(a[3]), "r"(b0), "r"(b1));
}
__device__ __forceinline__ uint32_t pack2(float a, float b) {
    __nv_bfloat16 h0 = __float2bfloat16(a), h1 = __float2bfloat16(b);
    return (uint32_t)__bfloat16_as_ushort(h0) | ((uint32_t)__bfloat16_as_ushort(h1) << 16);
}

// ---------------------------------------------------------------------------
// Kernel 0: zero output + reset counters
// ---------------------------------------------------------------------------
__global__ void zero_kernel(float4* __restrict__ out) {
    int i = blockIdx.x * blockDim.x + threadIdx.x;
    out[i] = make_float4(0.f, 0.f, 0.f, 0.f);
    if (blockIdx.x == 0 && threadIdx.x < EE) g_cnt[threadIdx.x] = 0;
}

// ---------------------------------------------------------------------------
// Kernel 1: router (fp32, validated round 1)
// ---------------------------------------------------------------------------
__global__ __launch_bounds__(256) void router_kernel(const float* __restrict__ x,
                                                     const float* __restrict__ rw) {
    int n = blockIdx.x, tid = threadIdx.x;
    const float* xr = x + (size_t)n * DD;
    float acc[EE];
#pragma unroll
    for (int e = 0; e < EE; e++) acc[e] = 0.f;
    for (int i = tid; i < DD; i += 256) {
        float xv = xr[i];
#pragma unroll
        for (int e = 0; e < EE; e++) acc[e] += xv * rw[e * DD + i];
    }
#pragma unroll
    for (int e = 0; e < EE; e++)
#pragma unroll
        for (int o = 16; o > 0; o >>= 1) acc[e] += __shfl_down_sync(0xffffffffu, acc[e], o);

    __shared__ float sm[8][EE];
    int warp = tid >> 5, lane = tid & 31;
    if (lane == 0)
#pragma unroll
        for (int e = 0; e < EE; e++) sm[warp][e] = acc[e];
    __syncthreads();

    if (tid == 0) {
        float logits[EE];
#pragma unroll
        for (int e = 0; e < EE; e++) {
            float s = 0.f;
#pragma unroll
            for (int w = 0; w < 8; w++) s += sm[w][e];
            logits[e] = s;
        }
        int i0 = 0; float v0 = logits[0];
#pragma unroll
        for (int e = 1; e < EE; e++) if (logits[e] > v0) { v0 = logits[e]; i0 = e; }
        int i1 = 0; float v1 = -3.0e38f;
#pragma unroll
        for (int e = 0; e < EE; e++) if (e != i0 && logits[e] > v1) { v1 = logits[e]; i1 = e; }
        float ex = __expf(v1 - v0);
        float g0 = 1.f / (1.f + ex);
        float g1 = ex * g0;
        int p0 = atomicAdd(&g_cnt[i0], 1);
        g_tok[i0 * NN + p0] = n;  g_gate[i0 * NN + p0] = g0;
        int p1 = atomicAdd(&g_cnt[i1], 1);
        g_tok[i1 * NN + p1] = n;  g_gate[i1 * NN + p1] = g1;
    }
}

// ---------------------------------------------------------------------------
// Kernel 2: gather tokens per expert, split fp32 -> bf16 hi/lo, pad to 128
// ---------------------------------------------------------------------------
__global__ __launch_bounds__(256) void gather_kernel(const float* __restrict__ x) {
    int e = blockIdx.y, slot = blockIdx.x;
    int cnt = g_cnt[e];
    int pad = (cnt + 127) & ~127;  if (pad > NN) pad = NN;
    if (slot >= pad) return;
    size_t dst = ((size_t)e * NN + slot) * DD;
    int i = threadIdx.x;            // 4 elems each
    if (slot < cnt) {
        int tok = g_tok[e * NN + slot];
        float4 v = ((const float4*)(x + (size_t)tok * DD))[i];
        __nv_bfloat16 h0 = __float2bfloat16(v.x), h1 = __float2bfloat16(v.y);
        __nv_bfloat16 h2 = __float2bfloat16(v.z), h3 = __float2bfloat16(v.w);
        uint2 hw, lw;
        hw.x = (uint32_t)__bfloat16_as_ushort(h0) | ((uint32_t)__bfloat16_as_ushort(h1) << 16);
        hw.y = (uint32_t)__bfloat16_as_ushort(h2) | ((uint32_t)__bfloat16_as_ushort(h3) << 16);
        lw.x = pack2(v.x - __bfloat162float(h0), v.y - __bfloat162float(h1));
        lw.y = pack2(v.z - __bfloat162float(h2), v.w - __bfloat162float(h3));
        ((uint2*)(g_xg_hi + dst))[i] = hw;
        ((uint2*)(g_xg_lo + dst))[i] = lw;
    } else {
        ((uint2*)(g_xg_hi + dst))[i] = make_uint2(0, 0);
        ((uint2*)(g_xg_lo + dst))[i] = make_uint2(0, 0);
    }
}

// ---------------------------------------------------------------------------
// Kernels 3/4: transpose + split weights  [E][R][C] fp32 -> [E][C][R] bf16 hi/lo
// ---------------------------------------------------------------------------
template<int R, int C, int WHICH>
__global__ __launch_bounds__(256) void wsplit_kernel(const float* __restrict__ w) {
    __shared__ float t[32][33];
    int e = blockIdx.z;
    int c0 = blockIdx.x * 32, r0 = blockIdx.y * 32;
    const float* src = w + (size_t)e * R * C;
    int tx = threadIdx.x & 31, ty = threadIdx.x >> 5;
#pragma unroll
    for (int i = 0; i < 4; i++)
        t[ty + i * 8][tx] = src[(size_t)(r0 + ty + i * 8) * C + c0 + tx];
    __syncthreads();
    __nv_bfloat16* hi = (WHICH == 0) ? g_w1t_hi : g_w2t_hi;
    __nv_bfloat16* lo = (WHICH == 0) ? g_w1t_lo : g_w2t_lo;
#pragma unroll
    for (int i = 0; i < 4; i++) {
        float v = t[tx][ty + i * 8];
        size_t o = ((size_t)e * C + c0 + ty + i * 8) * R + r0 + tx;
        __nv_bfloat16 h = __float2bfloat16(v);
        hi[o] = h;
        lo[o] = __float2bfloat16(v - __bfloat162float(h));
    }
}

// ---------------------------------------------------------------------------
// mma.sync grouped GEMM.  D[128x128] += A[128xK] * B^T[128xK], bf16 hi/lo split.
// smem element (m,k) of a 128x32 plane at:  m*64 + (((k>>3) ^ ((m>>1)&3))<<4) + (k&7)*2
// planes per stage: Ahi @0, Alo @8K, Bhi @16K, Blo @24K
// ---------------------------------------------------------------------------
template<int KTOT, bool IS_G1>
__global__ __launch_bounds__(256, 1) void gemm_mma(float* __restrict__ out) {
    constexpr int KC = KTOT / TK;
    int e   = blockIdx.z;
    int cnt = g_cnt[e];
    int m0  = blockIdx.y * TM;
    if (m0 >= cnt) return;
    int n0  = blockIdx.x * TN;

    extern __shared__ char smem[];
    uint32_t sb = smem_u32(smem);

    const __nv_bfloat16 *Ahi, *Alo, *Bhi, *Blo;
    if (IS_G1) {
        Ahi = g_xg_hi + ((size_t)e * NN + m0) * KTOT;
        Alo = g_xg_lo + ((size_t)e * NN + m0) * KTOT;
        Bhi = g_w1t_hi + ((size_t)e * HH + n0) * KTOT;
        Blo = g_w1t_lo + ((size_t)e * HH + n0) * KTOT;
    } else {
        Ahi = g_h_hi + ((size_t)e * NN + m0) * KTOT;
        Alo = g_h_lo + ((size_t)e * NN + m0) * KTOT;
        Bhi = g_w2t_hi + ((size_t)e * DD + n0) * KTOT;
        Blo = g_w2t_lo + ((size_t)e * DD + n0) * KTOT;
    }

    int tid = threadIdx.x;
    // ---- cp.async mapping: thread -> (row, two 16B chunks) per plane ----
    int lrow = tid >> 1;
    int lc0  = (tid & 1) * 2;                 // 16B-col 0 or 2
    int swl  = (lrow >> 1) & 3;
    uint32_t drow = (uint32_t)lrow * 64;
    uint32_t d0 = drow + (uint32_t)((lc0 ^ swl) << 4);
    uint32_t d1 = drow + (uint32_t)(((lc0 + 1) ^ swl) << 4);
    size_t arow = (size_t)lrow * KTOT;

    auto issue = [&](int j) {
        uint32_t st = sb + (uint32_t)(j & (STAGES - 1)) * STAGE_BYTES;
        int kb = j * TK + lc0 * 8;
        cp16(st + d0,         Ahi + arow + kb);
        cp16(st + d1,         Ahi + arow + kb + 8);
        cp16(st + 8192 + d0,  Alo + arow + kb);
        cp16(st + 8192 + d1,  Alo + arow + kb + 8);
        cp16(st + 16384 + d0, Bhi + arow + kb);
        cp16(st + 16384 + d1, Bhi + arow + kb + 8);
        cp16(st + 24576 + d0, Blo + arow + kb);
        cp16(st + 24576 + d1, Blo + arow + kb + 8);
    };

    issue(0); CP_COMMIT();
    issue(1); CP_COMMIT();
    issue(2); CP_COMMIT();

    // ---- warp / lane geometry ----
    int wid = tid >> 5, lane = tid & 31;
    int wm = wid & 3;          // 4 warps over M: rows wm*32
    int wn = wid >> 2;         // 2 warps over N: cols wn*64
    int li = lane >> 3;        // ldmatrix matrix id 0..3
    int lr = lane & 7;
    int kadd = li >> 1;        // +1 16B-unit for k+8 half
    int rsel = (li & 1) * 8 + lr;

    // per-lane ldmatrix row constants (A: 2 m-tiles, B: 4 n-tile-pairs)
    uint32_t abase[2]; int asw[2];
#pragma unroll
    for (int mt = 0; mt < 2; mt++) {
        int m = wm * 32 + mt * 16 + rsel;
        abase[mt] = (uint32_t)m * 64;
        asw[mt] = (m >> 1) & 3;
    }
    uint32_t bbase[4]; int bsw[4];
#pragma unroll
    for (int p = 0; p < 4; p++) {
        int n = wn * 64 + p * 16 + rsel;
        bbase[p] = (uint32_t)n * 64;
        bsw[p] = (n >> 1) & 3;
    }

    float acc[2][8][4];
#pragma unroll
    for (int a = 0; a < 2; a++)
#pragma unroll
        for (int b = 0; b < 8; b++)
#pragma unroll
            for (int c = 0; c < 4; c++) acc[a][b][c] = 0.f;

    for (int j = 0; j < KC; j++) {
        CP_WAIT(2);
        __syncthreads();
        if (j + 3 < KC) issue(j + 3);
        CP_COMMIT();                           // commit every iter (empty ok) to keep counts aligned
        uint32_t st = sb + (uint32_t)(j & (STAGES - 1)) * STAGE_BYTES;
#pragma unroll
        for (int kq = 0; kq < 4; kq += 2) {    // two k16 halves, kq = k16>>3
            uint32_t ahi[2][4], alo[2][4], bh[4][4], bl[4][4];
#pragma unroll
            for (int mt = 0; mt < 2; mt++) {
                uint32_t off = abase[mt] + (uint32_t)((((kq + kadd) ^ asw[mt])) << 4);
                ldsm4(ahi[mt], st + off);
                ldsm4(alo[mt], st + 8192 + off);
            }
#pragma unroll
            for (int p = 0; p < 4; p++) {
                uint32_t off = bbase[p] + (uint32_t)((((kq + kadd) ^ bsw[p])) << 4);
                ldsm4(bh[p], st + 16384 + off);
                ldsm4(bl[p], st + 24576 + off);
            }
#pragma unroll
            for (int mt = 0; mt < 2; mt++)
#pragma unroll
                for (int q = 0; q < 8; q++) {
                    int p = q >> 1, s = q & 1;
                    mma16816(acc[mt][q], ahi[mt], bh[p][s], bh[p][2 + s]);
                    mma16816(acc[mt][q], ahi[mt], bl[p][s], bl[p][2 + s]);
                    mma16816(acc[mt][q], alo[mt], bh[p][s], bh[p][2 + s]);
                }
        }
        __syncthreads();
    }

    // ---- epilogue ----
    int r4 = lane >> 2, cpair = (lane & 3) * 2;
    if (IS_G1) {
#pragma unroll
        for (int mt = 0; mt < 2; mt++) {
            int gm = m0 + wm * 32 + mt * 16;
#pragma unroll
            for (int q = 0; q < 8; q++) {
                int gn = n0 + wn * 64 + q * 8 + cpair;
#pragma unroll
                for (int half = 0; half < 2; half++) {
                    int row = gm + r4 + half * 8;
                    float v0 = acc[mt][q][half * 2 + 0];
                    float v1 = acc[mt][q][half * 2 + 1];
                    v0 = fmaxf(v0, 0.f); v0 *= v0;
                    v1 = fmaxf(v1, 0.f); v1 *= v1;
                    __nv_bfloat16 h0 = __float2bfloat16(v0), h1 = __float2bfloat16(v1);
                    uint32_t hw = (uint32_t)__bfloat16_as_ushort(h0) |
                                  ((uint32_t)__bfloat16_as_ushort(h1) << 16);
                    uint32_t lw = pack2(v0 - __bfloat162float(h0), v1 - __bfloat162float(h1));
                    size_t o = ((size_t)e * NN + row) * HH + gn;
                    *(uint32_t*)(g_h_hi + o) = hw;
                    *(uint32_t*)(g_h_lo + o) = lw;
                }
            }
        }
    } else {
#pragma unroll
        for (int mt = 0; mt < 2; mt++) {
            int gm = m0 + wm * 32 + mt * 16;
            int   tokh[2];
            float gth[2];
#pragma unroll
            for (int half = 0; half < 2; half++) {
                int slot = gm + r4 + half * 8;
                bool ok = slot < cnt;
                tokh[half] = ok ? g_tok[e * NN + slot] : -1;
                gth[half]  = ok ? g_gate[e * NN + slot] : 0.f;
            }
#pragma unroll
            for (int q = 0; q < 8; q++) {
                int gn = n0 + wn * 64 + q * 8 + cpair;
#pragma unroll
                for (int half = 0; half < 2; half++) {
                    if (tokh[half] >= 0) {
                        float* orow = out + (size_t)tokh[half] * DD + gn;
                        atomicAdd(orow,     gth[half] * acc[mt][q][half * 2 + 0]);
                        atomicAdd(orow + 1, gth[half] * acc[mt][q][half * 2 + 1]);
                    }
                }
            }
        }
    }
}

// ---------------------------------------------------------------------------
extern "C" void kernel_launch(void* const* d_in, const int* in_sizes, int n_in,
                              void* d_out, int out_size) {
    const float* x  = (const float*)d_in[0];   // (B,T,D)
    const float* rw = (const float*)d_in[1];   // (E,D)
    const float* w1 = (const float*)d_in[2];   // (E,D,H)
    const float* w2 = (const float*)d_in[3];   // (E,H,D)
    float* out = (float*)d_out;                // (B,T,D) fp32

    cudaFuncSetAttribute(gemm_mma<DD, true>,  cudaFuncAttributeMaxDynamicSharedMemorySize, SMEM_BYTES);
    cudaFuncSetAttribute(gemm_mma<HH, false>, cudaFuncAttributeMaxDynamicSharedMemorySize, SMEM_BYTES);

    int zblocks = out_size / (4 * 256);
    zero_kernel<<<zblocks, 256>>>((float4*)out);
    router_kernel<<<NN, 256>>>(x, rw);
    wsplit_kernel<DD, HH, 0><<<dim3(HH / 32, DD / 32, EE), 256>>>(w1);
    wsplit_kernel<HH, DD, 1><<<dim3(DD / 32, HH / 32, EE), 256>>>(w2);
    gather_kernel<<<dim3(NN, EE), 256>>>(x);
    gemm_mma<DD, true><<<dim3(HH / TN, NN / TM, EE), 256, SMEM_BYTES>>>(nullptr);
    gemm_mma<HH, false><<<dim3(DD / TN, NN / TM, EE), 256, SMEM_BYTES>>>(out);
}